// round 4
// baseline (speedup 1.0000x reference)
#include <cuda_runtime.h>

// FSQ: x (64, 32768, 4) fp32. N = 2097152 tokens, LEVELS = [8,5,5,5].
// out fp32 planes: out[d*N + n] = q_d, out[4*N + n] = code.
// 8 tokens per thread: 8x LDG.128 front-batched, 10x STG.128 (2 per plane).
// Quantizer: (tanh(x)+1)/2 = rcp(1+ex2(-2x*log2e)); idx = rint(r*(L-1)).

#define FSQ_N (64 * 32768)
#define TOK_PER_THREAD 8
#define NTHREADS 256
#define TOTAL_THREADS (FSQ_N / TOK_PER_THREAD)   // 262144
#define NBLOCKS (TOTAL_THREADS / NTHREADS)       // 1024

__device__ __forceinline__ float fast_ex2(float x) {
    float y;
    asm("ex2.approx.f32 %0, %1;" : "=f"(y) : "f"(x));
    return y;
}
__device__ __forceinline__ float fast_rcp(float x) {
    float y;
    asm("rcp.approx.f32 %0, %1;" : "=f"(y) : "f"(x));
    return y;
}

__device__ __forceinline__ int quant(float x, float scale, float step, float& q) {
    const float NEG2LOG2E = -2.8853900817779268f;  // -2*log2(e)
    float e = fast_ex2(x * NEG2LOG2E);             // e^(-2x)
    float r = fast_rcp(1.0f + e);                  // (tanh(x)+1)/2
    int idx = __float2int_rn(r * scale);
    q = (float)idx * step - 1.0f;
    return idx;
}

__device__ __forceinline__ void do_token(const float4& v, float& o0, float& o1,
                                         float& o2, float& o3, float& oc) {
    int i0 = quant(v.x, 7.0f, 2.0f / 7.0f, o0);
    int i1 = quant(v.y, 4.0f, 0.5f, o1);
    int i2 = quant(v.z, 4.0f, 0.5f, o2);
    int i3 = quant(v.w, 4.0f, 0.5f, o3);
    oc = (float)(i0 + 8 * i1 + 40 * i2 + 200 * i3);
}

__global__ __launch_bounds__(NTHREADS) void fsq_kernel(const float4* __restrict__ x4,
                                                       float4* __restrict__ out4) {
    int t = blockIdx.x * NTHREADS + threadIdx.x;   // one thread = 8 tokens

    // Front-batched loads: 8 independent LDG.128 in flight.
    float4 v[TOK_PER_THREAD];
#pragma unroll
    for (int k = 0; k < TOK_PER_THREAD; k++)
        v[k] = x4[TOK_PER_THREAD * t + k];

    // z[d][pair] : plane d, two float4 output words (tokens 0-3, 4-7)
    float4 z[5][2];
#pragma unroll
    for (int p = 0; p < 2; p++) {
        do_token(v[4 * p + 0], z[0][p].x, z[1][p].x, z[2][p].x, z[3][p].x, z[4][p].x);
        do_token(v[4 * p + 1], z[0][p].y, z[1][p].y, z[2][p].y, z[3][p].y, z[4][p].y);
        do_token(v[4 * p + 2], z[0][p].z, z[1][p].z, z[2][p].z, z[3][p].z, z[4][p].z);
        do_token(v[4 * p + 3], z[0][p].w, z[1][p].w, z[2][p].w, z[3][p].w, z[4][p].w);
    }

    const int PN4 = FSQ_N / 4;   // plane size in float4 units
#pragma unroll
    for (int d = 0; d < 5; d++) {
#pragma unroll
        for (int p = 0; p < 2; p++)
            out4[d * PN4 + 2 * t + p] = z[d][p];
    }
}

extern "C" void kernel_launch(void* const* d_in, const int* in_sizes, int n_in,
                              void* d_out, int out_size) {
    const float4* x4 = (const float4*)d_in[0];
    float4* out4 = (float4*)d_out;
    fsq_kernel<<<NBLOCKS, NTHREADS>>>(x4, out4);
}

// round 5
// speedup vs baseline: 1.6566x; 1.6566x over previous
#include <cuda_runtime.h>

// FSQ: x (64, 32768, 4) fp32. N = 2097152 tokens, LEVELS = [8,5,5,5].
// out fp32 planes: out[d*N + n] = q_d, out[4*N + n] = code (as float).
// One thread = 4 tokens: 2x LDG.256 (contiguous 64B), 5x STG.128 (one
// fully-coalesced float4 per plane per warp).
// Quantizer: (tanh(x)+1)/2 = rcp(1+ex2(-2x*log2e)); idx = rint(r*(L-1)).

#define FSQ_N (64 * 32768)
#define NTHREADS 256
#define NBLOCKS (FSQ_N / 4 / NTHREADS)   // 2048

__device__ __forceinline__ float fast_ex2(float x) {
    float y;
    asm("ex2.approx.f32 %0, %1;" : "=f"(y) : "f"(x));
    return y;
}
__device__ __forceinline__ float fast_rcp(float x) {
    float y;
    asm("rcp.approx.f32 %0, %1;" : "=f"(y) : "f"(x));
    return y;
}

__device__ __forceinline__ int quant(float x, float scale, float step, float& q) {
    const float NEG2LOG2E = -2.8853900817779268f;  // -2*log2(e)
    float e = fast_ex2(x * NEG2LOG2E);             // e^(-2x)
    float r = fast_rcp(1.0f + e);                  // (tanh(x)+1)/2
    int idx = __float2int_rn(r * scale);
    q = (float)idx * step - 1.0f;
    return idx;
}

__device__ __forceinline__ void do_token(float x, float y, float z, float w,
                                         float& o0, float& o1, float& o2,
                                         float& o3, float& oc) {
    int i0 = quant(x, 7.0f, 2.0f / 7.0f, o0);
    int i1 = quant(y, 4.0f, 0.5f, o1);
    int i2 = quant(z, 4.0f, 0.5f, o2);
    int i3 = quant(w, 4.0f, 0.5f, o3);
    oc = (float)(i0 + 8 * i1 + 40 * i2 + 200 * i3);
}

// 256-bit global load (sm_100+): 8 fp32 per thread, contiguous.
__device__ __forceinline__ void ldg256(const float* p, float* r) {
    asm volatile(
        "ld.global.nc.v8.f32 {%0, %1, %2, %3, %4, %5, %6, %7}, [%8];"
        : "=f"(r[0]), "=f"(r[1]), "=f"(r[2]), "=f"(r[3]),
          "=f"(r[4]), "=f"(r[5]), "=f"(r[6]), "=f"(r[7])
        : "l"(p));
}

__global__ __launch_bounds__(NTHREADS) void fsq_kernel(const float* __restrict__ x,
                                                       float4* __restrict__ out4) {
    int t = blockIdx.x * NTHREADS + threadIdx.x;   // one thread = 4 tokens (16 floats)

    float v[16];
    ldg256(x + 16 * t, v);
    ldg256(x + 16 * t + 8, v + 8);

    float4 z0, z1, z2, z3, zc;
    do_token(v[0],  v[1],  v[2],  v[3],  z0.x, z1.x, z2.x, z3.x, zc.x);
    do_token(v[4],  v[5],  v[6],  v[7],  z0.y, z1.y, z2.y, z3.y, zc.y);
    do_token(v[8],  v[9],  v[10], v[11], z0.z, z1.z, z2.z, z3.z, zc.z);
    do_token(v[12], v[13], v[14], v[15], z0.w, z1.w, z2.w, z3.w, zc.w);

    const int PN4 = FSQ_N / 4;   // plane size in float4 units
    out4[0 * PN4 + t] = z0;
    out4[1 * PN4 + t] = z1;
    out4[2 * PN4 + t] = z2;
    out4[3 * PN4 + t] = z3;
    out4[4 * PN4 + t] = zc;
}

extern "C" void kernel_launch(void* const* d_in, const int* in_sizes, int n_in,
                              void* d_out, int out_size) {
    const float* x = (const float*)d_in[0];
    float4* out4 = (float4*)d_out;
    fsq_kernel<<<NBLOCKS, NTHREADS>>>(x, out4);
}